// round 1
// baseline (speedup 1.0000x reference)
#include <cuda_runtime.h>
#include <cuda_bf16.h>
#include <math.h>

// Problem constants
#define B   32
#define C   64      // in == out channels
#define HW  64      // input H == W, also pooled H == W
#define NTILE 16    // row tiles of 4 pooled rows each

// smem layout (floats)
#define XS_STRIDE_R  68
#define XS_STRIDE_IC (6*68)                 // 408
#define XS_FLOATS   (C * XS_STRIDE_IC)      // 26112
#define WS_FLOATS   (C * 16 * 16)           // 16384 : [ic][oc16][tap]
#define RED_FLOATS  (16 * 64)               // 1024
#define SMEM_FLOATS (XS_FLOATS + WS_FLOATS + RED_FLOATS)
#define SMEM_BYTES  (SMEM_FLOATS * 4)       // 174080

// partial sums: [b][oc][tile]
__device__ float g_part[B][C][NTILE];

__global__ __launch_bounds__(256)
void fused_convtmp_kernel(const float* __restrict__ x,
                          const float* __restrict__ w,
                          const float* __restrict__ bias)
{
    extern __shared__ float smem[];
    float* xs  = smem;                       // [64][6][68]
    float* ws  = smem + XS_FLOATS;           // [64][16][16]
    float* red = ws + WS_FLOATS;             // [16][64]

    const int tid  = threadIdx.x;
    const int tile = blockIdx.x;             // 0..15
    const int b    = blockIdx.y;             // 0..31
    const int pr0  = tile * 4;

    // ---- stage x slab: ic in [0,64), rows ih = pr0-1 .. pr0+4, cols iw = -1..64 ----
    const float* xb = x + (size_t)b * C * HW * HW;
    for (int idx = tid; idx < C * 6 * 66; idx += 256) {
        int ic  = idx / 396;
        int rem = idx - ic * 396;
        int r   = rem / 66;
        int c   = rem - r * 66;
        int ih  = pr0 - 1 + r;
        int iw  = c - 1;
        float v = 0.f;
        if (ih >= 0 && ih < HW && iw >= 0 && iw < HW)
            v = xb[(ic * HW + ih) * HW + iw];
        xs[ic * XS_STRIDE_IC + r * XS_STRIDE_R + c] = v;
    }

    const int ocsub = tid >> 6;              // 0..3
    const int pg    = tid & 63;              // 0..63
    const int lr    = pg >> 4;               // pooled row within tile 0..3
    const int pc0   = (pg & 15) * 4;         // first pooled col of this thread

    for (int pass = 0; pass < 4; ++pass) {
        __syncthreads();
        // stage weights for oc = pass*16 .. pass*16+15 ; w layout [ic][oc][kh][kw]
        for (int idx = tid; idx < WS_FLOATS; idx += 256) {
            int ic  = idx >> 8;              // /256
            int rem = idx & 255;             // oc16*16 + tap
            ws[idx] = w[ic * (C * 16) + pass * 256 + rem];
        }
        __syncthreads();

        float acc[4][4][4];                  // [oc j][pixel p][parity q]
        #pragma unroll
        for (int j = 0; j < 4; ++j)
            #pragma unroll
            for (int p = 0; p < 4; ++p)
                #pragma unroll
                for (int q = 0; q < 4; ++q) acc[j][p][q] = 0.f;

        for (int ic = 0; ic < C; ++ic) {
            const float* xr = xs + ic * XS_STRIDE_IC + lr * XS_STRIDE_R + pc0;
            float xv[3][6];
            #pragma unroll
            for (int i = 0; i < 3; ++i) {
                float4 v4 = *(const float4*)(xr + i * XS_STRIDE_R);
                float2 v2 = *(const float2*)(xr + i * XS_STRIDE_R + 4);
                xv[i][0] = v4.x; xv[i][1] = v4.y; xv[i][2] = v4.z;
                xv[i][3] = v4.w; xv[i][4] = v2.x; xv[i][5] = v2.y;
            }
            const float* wr = ws + ic * 256 + ocsub * 64;   // 4 oc x 16 taps
            #pragma unroll
            for (int j = 0; j < 4; ++j) {
                float wv[16];
                #pragma unroll
                for (int t = 0; t < 16; ++t) wv[t] = wr[j * 16 + t];
                #pragma unroll
                for (int p = 0; p < 4; ++p) {
                    // q=0: oh even, ow even  (kh in {1,3}, kw in {1,3})
                    acc[j][p][0] += xv[1][p+1]*wv[5]  + xv[1][p+0]*wv[7]
                                  + xv[0][p+1]*wv[13] + xv[0][p+0]*wv[15];
                    // q=1: oh even, ow odd   (kw in {0,2})
                    acc[j][p][1] += xv[1][p+2]*wv[4]  + xv[1][p+1]*wv[6]
                                  + xv[0][p+2]*wv[12] + xv[0][p+1]*wv[14];
                    // q=2: oh odd, ow even   (kh in {0,2})
                    acc[j][p][2] += xv[2][p+1]*wv[1]  + xv[2][p+0]*wv[3]
                                  + xv[1][p+1]*wv[9]  + xv[1][p+0]*wv[11];
                    // q=3: oh odd, ow odd
                    acc[j][p][3] += xv[2][p+2]*wv[0]  + xv[2][p+1]*wv[2]
                                  + xv[1][p+2]*wv[8]  + xv[1][p+1]*wv[10];
                }
            }
        }

        // ---- epilogue: max over 2x2, +bias, hardtanh, per-thread pixel sum ----
        float hsum[4];
        #pragma unroll
        for (int j = 0; j < 4; ++j) {
            int oc   = pass * 16 + ocsub * 4 + j;
            float bi = bias[oc];
            float s  = 0.f;
            #pragma unroll
            for (int p = 0; p < 4; ++p) {
                float m = fmaxf(fmaxf(acc[j][p][0], acc[j][p][1]),
                                fmaxf(acc[j][p][2], acc[j][p][3])) + bi;
                m = fminf(fmaxf(m, -1.f), 1.f);
                s += m;
            }
            hsum[j] = s;
        }
        #pragma unroll
        for (int j = 0; j < 4; ++j)
            red[(ocsub * 4 + j) * 64 + pg] = hsum[j];
        __syncthreads();

        // deterministic tree reduction: 16 threads per oc16
        {
            int oc16 = tid >> 4;
            int l    = tid & 15;
            const float* rr = red + oc16 * 64;
            float v = rr[l] + rr[l + 16] + rr[l + 32] + rr[l + 48];
            v += __shfl_down_sync(0xffffffffu, v, 8, 16);
            v += __shfl_down_sync(0xffffffffu, v, 4, 16);
            v += __shfl_down_sync(0xffffffffu, v, 2, 16);
            v += __shfl_down_sync(0xffffffffu, v, 1, 16);
            if (l == 0)
                g_part[b][pass * 16 + oc16][tile] = v;
        }
        __syncthreads();
    }
}

__global__ void finalize_kernel(float* __restrict__ out)
{
    int b  = blockIdx.x;
    int oc = threadIdx.x;
    float s = 0.f;
    #pragma unroll
    for (int t = 0; t < NTILE; ++t) s += g_part[b][oc][t];
    out[b * C + oc] = tanhf(s * (1.0f / 4096.0f));
}

extern "C" void kernel_launch(void* const* d_in, const int* in_sizes, int n_in,
                              void* d_out, int out_size)
{
    const float* x    = (const float*)d_in[0];
    const float* w    = (const float*)d_in[1];
    const float* bias = (const float*)d_in[2];
    float* out = (float*)d_out;

    cudaFuncSetAttribute(fused_convtmp_kernel,
                         cudaFuncAttributeMaxDynamicSharedMemorySize, SMEM_BYTES);

    dim3 grid(NTILE, B);
    fused_convtmp_kernel<<<grid, 256, SMEM_BYTES>>>(x, w, bias);
    finalize_kernel<<<B, C>>>(out);
}

// round 2
// speedup vs baseline: 1.1537x; 1.1537x over previous
#include <cuda_runtime.h>
#include <cuda_bf16.h>
#include <math.h>

// Problem constants
#define B   32
#define C   64      // in == out channels
#define HW  64      // input H == W, also pooled H == W
#define NTILE 16    // row tiles of 4 pooled rows each

// smem layout
#define XS_STRIDE_R  68
#define XS_STRIDE_IC (6*68)                 // 408
#define XS_FLOATS   (C * XS_STRIDE_IC)      // 26112 floats = 104448 B
#define WS2_DOUBLES (C * 8 * 16)            // 8192 doubles = 65536 B  [ic][ocpair][tap]
#define RED_FLOATS  (16 * 64)               // 1024 floats = 4096 B
#define SMEM_BYTES  (XS_FLOATS*4 + WS2_DOUBLES*8 + RED_FLOATS*4)   // 174080

// partial sums: [b][oc][tile]
__device__ float g_part[B][C][NTILE];

// ---- packed f32x2 helpers (Blackwell) ----
__device__ __forceinline__ double pk2(float lo, float hi) {
    double d; asm("mov.b64 %0, {%1,%2};" : "=d"(d) : "f"(lo), "f"(hi)); return d;
}
__device__ __forceinline__ void fma2(double& acc, double a, double b) {
    asm("fma.rn.f32x2 %0, %1, %2, %0;" : "+d"(acc) : "d"(a), "d"(b));
}
__device__ __forceinline__ void upk(double d, float& lo, float& hi) {
    asm("mov.b64 {%0,%1}, %2;" : "=f"(lo), "=f"(hi) : "d"(d));
}

__global__ __launch_bounds__(256)
void fused_convtmp_kernel(const float* __restrict__ x,
                          const float* __restrict__ w,
                          const float* __restrict__ bias)
{
    extern __shared__ float smem[];
    float*  xs  = smem;                                   // [64][6][68]
    double* ws2 = (double*)(smem + XS_FLOATS);            // [64][8][16] oc-pair packed
    float*  red = (float*)(ws2 + WS2_DOUBLES);            // [16][64]

    const int tid  = threadIdx.x;
    const int tile = blockIdx.x;             // 0..15
    const int b    = blockIdx.y;             // 0..31
    const int pr0  = tile * 4;

    // ---- stage x slab: ic in [0,64), rows ih = pr0-1 .. pr0+4, cols iw = -1..64 ----
    const float* xb = x + (size_t)b * C * HW * HW;
    for (int idx = tid; idx < C * 6 * 66; idx += 256) {
        int ic  = idx / 396;
        int rem = idx - ic * 396;
        int r   = rem / 66;
        int c   = rem - r * 66;
        int ih  = pr0 - 1 + r;
        int iw  = c - 1;
        float v = 0.f;
        if (ih >= 0 && ih < HW && iw >= 0 && iw < HW)
            v = xb[(ic * HW + ih) * HW + iw];
        xs[ic * XS_STRIDE_IC + r * XS_STRIDE_R + c] = v;
    }

    const int ocsub = tid >> 6;              // 0..3  -> 4 oc per thread (2 pairs)
    const int pg    = tid & 63;              // 0..63
    const int lr    = pg >> 4;               // pooled row within tile 0..3
    const int pc0   = (pg & 15) * 4;         // first pooled col of this thread

    for (int pass = 0; pass < 4; ++pass) {
        __syncthreads();
        // stage oc-pair-packed weights for oc = pass*16 .. pass*16+15
        // w layout: [ic][oc][kh][kw]  (ic stride 64*16 = 1024)
        for (int idx = tid; idx < WS2_DOUBLES; idx += 256) {
            int ic  = idx >> 7;              // /128
            int rem = idx & 127;             // ocp*16 + tap
            int ocp = rem >> 4;
            int tap = rem & 15;
            const float* wp = w + ic * 1024 + (pass * 16 + ocp * 2) * 16 + tap;
            ws2[idx] = pk2(wp[0], wp[16]);
        }
        __syncthreads();

        double acc[2][4][4];                 // [oc-pair jp][pixel p][parity q], f32x2
        #pragma unroll
        for (int jp = 0; jp < 2; ++jp)
            #pragma unroll
            for (int p = 0; p < 4; ++p)
                #pragma unroll
                for (int q = 0; q < 4; ++q) acc[jp][p][q] = 0.0;

        for (int ic = 0; ic < C; ++ic) {
            const float* xr = xs + ic * XS_STRIDE_IC + lr * XS_STRIDE_R + pc0;
            float xv[3][6];
            #pragma unroll
            for (int i = 0; i < 3; ++i) {
                float4 v4 = *(const float4*)(xr + i * XS_STRIDE_R);
                float2 v2 = *(const float2*)(xr + i * XS_STRIDE_R + 4);
                xv[i][0] = v4.x; xv[i][1] = v4.y; xv[i][2] = v4.z;
                xv[i][3] = v4.w; xv[i][4] = v2.x; xv[i][5] = v2.y;
            }
            // duplicate each x value into an f32x2 broadcast operand
            double xd[3][6];
            #pragma unroll
            for (int i = 0; i < 3; ++i)
                #pragma unroll
                for (int c2 = 0; c2 < 6; ++c2)
                    xd[i][c2] = pk2(xv[i][c2], xv[i][c2]);

            const double* wr = ws2 + ic * 128 + ocsub * 32;   // 2 oc-pairs x 16 taps
            #pragma unroll
            for (int jp = 0; jp < 2; ++jp) {
                double wv[16];
                #pragma unroll
                for (int t = 0; t < 16; ++t) wv[t] = wr[jp * 16 + t];
                #pragma unroll
                for (int p = 0; p < 4; ++p) {
                    // q=0: oh even, ow even  (kh in {1,3}, kw in {1,3})
                    fma2(acc[jp][p][0], xd[1][p+1], wv[5]);
                    fma2(acc[jp][p][0], xd[1][p+0], wv[7]);
                    fma2(acc[jp][p][0], xd[0][p+1], wv[13]);
                    fma2(acc[jp][p][0], xd[0][p+0], wv[15]);
                    // q=1: oh even, ow odd   (kw in {0,2})
                    fma2(acc[jp][p][1], xd[1][p+2], wv[4]);
                    fma2(acc[jp][p][1], xd[1][p+1], wv[6]);
                    fma2(acc[jp][p][1], xd[0][p+2], wv[12]);
                    fma2(acc[jp][p][1], xd[0][p+1], wv[14]);
                    // q=2: oh odd, ow even   (kh in {0,2})
                    fma2(acc[jp][p][2], xd[2][p+1], wv[1]);
                    fma2(acc[jp][p][2], xd[2][p+0], wv[3]);
                    fma2(acc[jp][p][2], xd[1][p+1], wv[9]);
                    fma2(acc[jp][p][2], xd[1][p+0], wv[11]);
                    // q=3: oh odd, ow odd
                    fma2(acc[jp][p][3], xd[2][p+2], wv[0]);
                    fma2(acc[jp][p][3], xd[2][p+1], wv[2]);
                    fma2(acc[jp][p][3], xd[1][p+2], wv[8]);
                    fma2(acc[jp][p][3], xd[1][p+1], wv[10]);
                }
            }
        }

        // ---- epilogue: max over 2x2 (the 4 parities), +bias, hardtanh, pixel sum ----
        #pragma unroll
        for (int jp = 0; jp < 2; ++jp) {
            float s0 = 0.f, s1 = 0.f;
            int oc0 = pass * 16 + ocsub * 4 + jp * 2;
            float b0 = bias[oc0];
            float b1 = bias[oc0 + 1];
            #pragma unroll
            for (int p = 0; p < 4; ++p) {
                float q0l, q0h, q1l, q1h, q2l, q2h, q3l, q3h;
                upk(acc[jp][p][0], q0l, q0h);
                upk(acc[jp][p][1], q1l, q1h);
                upk(acc[jp][p][2], q2l, q2h);
                upk(acc[jp][p][3], q3l, q3h);
                float m0 = fmaxf(fmaxf(q0l, q1l), fmaxf(q2l, q3l)) + b0;
                float m1 = fmaxf(fmaxf(q0h, q1h), fmaxf(q2h, q3h)) + b1;
                s0 += fminf(fmaxf(m0, -1.f), 1.f);
                s1 += fminf(fmaxf(m1, -1.f), 1.f);
            }
            red[(ocsub * 4 + jp * 2 + 0) * 64 + pg] = s0;
            red[(ocsub * 4 + jp * 2 + 1) * 64 + pg] = s1;
        }
        __syncthreads();

        // deterministic tree reduction: 16 threads per oc of this pass
        {
            int oc16 = tid >> 4;
            int l    = tid & 15;
            const float* rr = red + oc16 * 64;
            float v = rr[l] + rr[l + 16] + rr[l + 32] + rr[l + 48];
            v += __shfl_down_sync(0xffffffffu, v, 8, 16);
            v += __shfl_down_sync(0xffffffffu, v, 4, 16);
            v += __shfl_down_sync(0xffffffffu, v, 2, 16);
            v += __shfl_down_sync(0xffffffffu, v, 1, 16);
            if (l == 0)
                g_part[b][pass * 16 + oc16][tile] = v;
        }
        __syncthreads();
    }
}

__global__ void finalize_kernel(float* __restrict__ out)
{
    int b  = blockIdx.x;
    int oc = threadIdx.x;
    float s = 0.f;
    #pragma unroll
    for (int t = 0; t < NTILE; ++t) s += g_part[b][oc][t];
    out[b * C + oc] = tanhf(s * (1.0f / 4096.0f));
}

extern "C" void kernel_launch(void* const* d_in, const int* in_sizes, int n_in,
                              void* d_out, int out_size)
{
    const float* x    = (const float*)d_in[0];
    const float* w    = (const float*)d_in[1];
    const float* bias = (const float*)d_in[2];
    float* out = (float*)d_out;

    cudaFuncSetAttribute(fused_convtmp_kernel,
                         cudaFuncAttributeMaxDynamicSharedMemorySize, SMEM_BYTES);

    dim3 grid(NTILE, B);
    fused_convtmp_kernel<<<grid, 256, SMEM_BYTES>>>(x, w, bias);
    finalize_kernel<<<B, C>>>(out);
}

// round 4
// speedup vs baseline: 6.6147x; 5.7336x over previous
#include <cuda_runtime.h>
#include <cuda_fp16.h>
#include <cstdint>
#include <math.h>

#define B_    32
#define C_    64
#define HW_   64
#define NTILE 16

// ---- smem layout ----
#define XS_HSTRIDE 72                        // halves per (R,px) row (144B, conflict-free)
#define XS_BYTES   (6*66*XS_HSTRIDE*2)       // 57024
#define QBUF_OFF   XS_BYTES
#define QPX        132                       // padded px stride (floats)
#define QBUF_BYTES (4*64*QPX*4)              // 135168
#define SMEM_TOTAL (QBUF_OFF + QBUF_BYTES)   // 192192

// fragment-ordered weights: [warpclass 8][reg-group 32][lane 32] (uint4 = 4 a-regs)
__device__ uint4 g_wfrag[8][32][32];
__device__ float g_part[B_][C_][NTILE];

__device__ __forceinline__ void mma16816(float* c, const uint4 a, uint32_t b0, uint32_t b1) {
    asm volatile("mma.sync.aligned.m16n8k16.row.col.f32.f16.f16.f32 "
        "{%0,%1,%2,%3}, {%4,%5,%6,%7}, {%8,%9}, {%0,%1,%2,%3};"
        : "+f"(c[0]), "+f"(c[1]), "+f"(c[2]), "+f"(c[3])
        : "r"(a.x), "r"(a.y), "r"(a.z), "r"(a.w), "r"(b0), "r"(b1));
}

// ---- prep: w[ic][oc][kh][kw] fp32 -> fragment-ordered fp16 table ----
__global__ void prep_wfrag(const float* __restrict__ w) {
    int idx = blockIdx.x * 256 + threadIdx.x;            // 8192 total
    if (idx >= 8192) return;
    int wc = idx >> 10, rg = (idx >> 5) & 31, lane = idx & 31;
    int q = wc >> 1, h = wc & 1;
    int kt = rg >> 3, j = (rg >> 1) & 3, mt = rg & 1;
    int jh = j >> 1, jw = j & 1;
    int a = q >> 1, bb = q & 1;
    int kh = a ? (jh ? 2 : 0) : (jh ? 3 : 1);
    int kw = bb ? (jw ? 2 : 0) : (jw ? 3 : 1);
    int tap = kh * 4 + kw;
    int g = lane >> 2, t = lane & 3;
    uint4 v;
    uint32_t* vp = (uint32_t*)&v;
    #pragma unroll
    for (int i = 0; i < 4; i++) {
        int oc = h * 32 + mt * 16 + g + 8 * (i & 1);
        int k  = kt * 16 + t * 2 + 8 * (i >> 1);
        __half2 hh = __floats2half2_rn(w[k * 1024 + oc * 16 + tap],
                                       w[(k + 1) * 1024 + oc * 16 + tap]);
        vp[i] = *(uint32_t*)&hh;
    }
    g_wfrag[wc][rg][lane] = v;
}

// ---- main fused kernel ----
__global__ void __launch_bounds__(256, 1)
fused_hmma_kernel(const float* __restrict__ x, const float* __restrict__ bias)
{
    extern __shared__ char smem[];
    __half* xs   = (__half*)smem;                        // [6][66][72]
    float*  qbuf = (float*)(smem + QBUF_OFF);            // [4][64][132]

    const int tid  = threadIdx.x;
    const int lane = tid & 31;
    const int wid  = tid >> 5;
    const int tile = blockIdx.x;
    const int b    = blockIdx.y;
    const int pr0  = tile * 4;

    // ---- stage x slab as fp16 [R][px][ic], zero-padded borders ----
    const float* xb = x + (size_t)b * C_ * HW_ * HW_;
    for (int ri = tid; ri < 384; ri += 256) {            // 6 rows * 64 ic
        int R = ri >> 6, ic = ri & 63, ih = pr0 - 1 + R;
        __half hv[66];
        #pragma unroll
        for (int p = 0; p < 66; p++) hv[p] = __float2half(0.f);
        if (ih >= 0 && ih < HW_) {
            const float4* src = (const float4*)(xb + ((size_t)ic * HW_ + ih) * HW_);
            #pragma unroll
            for (int p = 0; p < 16; p++) {
                float4 v = src[p];
                hv[1 + 4*p] = __float2half(v.x);
                hv[2 + 4*p] = __float2half(v.y);
                hv[3 + 4*p] = __float2half(v.z);
                hv[4 + 4*p] = __float2half(v.w);
            }
        }
        #pragma unroll
        for (int p = 0; p < 66; p++)
            xs[(R * 66 + p) * XS_HSTRIDE + ic] = hv[p];
    }
    __syncthreads();

    // ---- load all weight A-fragments into registers (128 regs) ----
    uint4 A[32];
    #pragma unroll
    for (int rg = 0; rg < 32; rg++) A[rg] = g_wfrag[wid][rg][lane];

    const int q = wid >> 1, h = wid & 1;
    const int a = q >> 1, bb = q & 1;
    const int ro0 = a ? 2 : 1, ro1 = a ? 1 : 0;          // jh=0, jh=1
    const int co0 = bb ? 2 : 1, co1 = bb ? 1 : 0;        // jw=0, jw=1
    const int g = lane >> 2, t = lane & 3;

    float bb8[8], psum8[8];
    #pragma unroll
    for (int ol = 0; ol < 8; ol++) { bb8[ol] = bias[wid * 8 + ol]; psum8[ol] = 0.f; }

    for (int hf = 0; hf < 2; hf++) {                     // two pooled-row pairs
        // ---- compute this warp's parity over 128 px, all 32 oc of its half ----
        for (int nt = 0; nt < 16; nt++) {
            int lr  = hf * 2 + (nt >> 3);
            int pc0 = (nt & 7) * 8;
            float acc0[4] = {0.f,0.f,0.f,0.f};
            float acc1[4] = {0.f,0.f,0.f,0.f};
            #pragma unroll
            for (int kt = 0; kt < 4; kt++) {
                uint32_t Bf[2][2][2];
                #pragma unroll
                for (int jh = 0; jh < 2; jh++) {
                    int R = lr + (jh ? ro1 : ro0);
                    #pragma unroll
                    for (int jw = 0; jw < 2; jw++) {
                        int px = pc0 + (jw ? co1 : co0) + g;
                        const __half* bp = xs + (R * 66 + px) * XS_HSTRIDE + kt * 16 + t * 2;
                        Bf[jh][jw][0] = *(const uint32_t*)bp;
                        Bf[jh][jw][1] = *(const uint32_t*)(bp + 8);
                    }
                }
                #pragma unroll
                for (int jh = 0; jh < 2; jh++)
                    #pragma unroll
                    for (int jw = 0; jw < 2; jw++) {
                        int j = jh * 2 + jw;
                        mma16816(acc0, A[(kt * 4 + j) * 2 + 0], Bf[jh][jw][0], Bf[jh][jw][1]);
                        mma16816(acc1, A[(kt * 4 + j) * 2 + 1], Bf[jh][jw][0], Bf[jh][jw][1]);
                    }
            }
            // store parity results: c0,c1 -> row g ; c2,c3 -> row g+8
            int pxh = (nt >> 3) * 64 + pc0 + t * 2;
            float* d0 = qbuf + (q * 64 + h * 32 + g) * QPX + pxh;
            *(float2*)d0              = make_float2(acc0[0], acc0[1]);
            *(float2*)(d0 + 8 * QPX)  = make_float2(acc0[2], acc0[3]);
            float* d1 = qbuf + (q * 64 + h * 32 + 16 + g) * QPX + pxh;
            *(float2*)d1              = make_float2(acc1[0], acc1[1]);
            *(float2*)(d1 + 8 * QPX)  = make_float2(acc1[2], acc1[3]);
        }
        __syncthreads();

        // ---- epilogue: warp w owns oc rows w*8..w*8+7; lane reads px lane*4..+3 ----
        #pragma unroll
        for (int ol = 0; ol < 8; ol++) {
            int oc = wid * 8 + ol;
            const float* base = qbuf + oc * QPX + lane * 4;
            float4 v0 = *(const float4*)(base + 0 * 64 * QPX);
            float4 v1 = *(const float4*)(base + 1 * 64 * QPX);
            float4 v2 = *(const float4*)(base + 2 * 64 * QPX);
            float4 v3 = *(const float4*)(base + 3 * 64 * QPX);
            float m, s = 0.f;
            m = fmaxf(fmaxf(v0.x, v1.x), fmaxf(v2.x, v3.x)) + bb8[ol];
            s += fminf(fmaxf(m, -1.f), 1.f);
            m = fmaxf(fmaxf(v0.y, v1.y), fmaxf(v2.y, v3.y)) + bb8[ol];
            s += fminf(fmaxf(m, -1.f), 1.f);
            m = fmaxf(fmaxf(v0.z, v1.z), fmaxf(v2.z, v3.z)) + bb8[ol];
            s += fminf(fmaxf(m, -1.f), 1.f);
            m = fmaxf(fmaxf(v0.w, v1.w), fmaxf(v2.w, v3.w)) + bb8[ol];
            s += fminf(fmaxf(m, -1.f), 1.f);
            psum8[ol] += s;
        }
        __syncthreads();
    }

    // ---- reduction: reuse qbuf as scratch [64 oc][32 lanes] ----
    float* red2 = qbuf;
    #pragma unroll
    for (int ol = 0; ol < 8; ol++)
        red2[(wid * 8 + ol) * 32 + lane] = psum8[ol];
    __syncthreads();
    if (tid < 64) {
        const float4* r = (const float4*)(red2 + tid * 32);
        float4 s4 = make_float4(0.f, 0.f, 0.f, 0.f);
        #pragma unroll
        for (int k = 0; k < 8; k++) {
            float4 v = r[k];
            s4.x += v.x; s4.y += v.y; s4.z += v.z; s4.w += v.w;
        }
        g_part[b][tid][tile] = (s4.x + s4.y) + (s4.z + s4.w);
    }
}

__global__ void finalize_kernel(float* __restrict__ out)
{
    int b  = blockIdx.x;
    int oc = threadIdx.x;
    float s = 0.f;
    #pragma unroll
    for (int t = 0; t < NTILE; ++t) s += g_part[b][oc][t];
    out[b * C_ + oc] = tanhf(s * (1.0f / 4096.0f));
}

extern "C" void kernel_launch(void* const* d_in, const int* in_sizes, int n_in,
                              void* d_out, int out_size)
{
    const float* x    = (const float*)d_in[0];
    const float* w    = (const float*)d_in[1];
    const float* bias = (const float*)d_in[2];
    float* out = (float*)d_out;

    cudaFuncSetAttribute(fused_hmma_kernel,
                         cudaFuncAttributeMaxDynamicSharedMemorySize, SMEM_TOTAL);

    prep_wfrag<<<32, 256>>>(w);
    fused_hmma_kernel<<<dim3(NTILE, B_), 256, SMEM_TOTAL>>>(x, bias);
    finalize_kernel<<<B_, C_>>>(out);
}

// round 5
// speedup vs baseline: 6.7783x; 1.0247x over previous
#include <cuda_runtime.h>
#include <cuda_fp16.h>
#include <cstdint>
#include <math.h>

#define B_    32
#define C_    64
#define HW_   64
#define NTILE 16

// ---- smem layout ----
#define XS_HSTRIDE 72                        // halves per (R,px) row (144B)
#define XS_BYTES   (6*66*XS_HSTRIDE*2)       // 57024
#define QBUF_OFF   XS_BYTES
#define QPX        132                       // padded px stride (floats)
#define QBUF_BYTES (4*64*QPX*4)              // 135168
#define SMEM_TOTAL (QBUF_OFF + QBUF_BYTES)   // 192192

// fragment-ordered B (weight) table: [warpclass 8][frag 64 = (kt*4+j)*4+ng][lane 32]
__device__ uint2 g_wfragB[8][64][32];
__device__ float g_part[B_][C_][NTILE];

__device__ __forceinline__ void mma_xw(float* c, const uint4 a, const uint2 b) {
    asm volatile("mma.sync.aligned.m16n8k16.row.col.f32.f16.f16.f32 "
        "{%0,%1,%2,%3}, {%4,%5,%6,%7}, {%8,%9}, {%0,%1,%2,%3};"
        : "+f"(c[0]), "+f"(c[1]), "+f"(c[2]), "+f"(c[3])
        : "r"(a.x), "r"(a.y), "r"(a.z), "r"(a.w), "r"(b.x), "r"(b.y));
}
__device__ __forceinline__ void ldsm_x4(uint4& d, uint32_t addr) {
    asm volatile("ldmatrix.sync.aligned.m8n8.x4.shared.b16 {%0,%1,%2,%3}, [%4];"
        : "=r"(d.x), "=r"(d.y), "=r"(d.z), "=r"(d.w) : "r"(addr));
}
__device__ __forceinline__ uint32_t smem_u32(const void* p) {
    uint32_t a;
    asm("{ .reg .u64 t; cvta.to.shared.u64 t, %1; cvt.u32.u64 %0, t; }" : "=r"(a) : "l"(p));
    return a;
}

// ---- prep: w[ic][oc][kh][kw] fp32 -> B-fragment fp16 table ----
__global__ void prep_wfragB(const float* __restrict__ w) {
    int idx = blockIdx.x * 256 + threadIdx.x;            // 8*64*32 = 16384
    if (idx >= 16384) return;
    int wc = idx >> 11, f = (idx >> 5) & 63, t = idx & 31;
    int q = wc >> 1, h = wc & 1;
    int kt = f >> 4, j = (f >> 2) & 3, ng = f & 3;
    int jh = j >> 1, jw = j & 1;
    int a = q >> 1, bb = q & 1;
    int kh = a ? (jh ? 2 : 0) : (jh ? 3 : 1);
    int kw = bb ? (jw ? 2 : 0) : (jw ? 3 : 1);
    int tap = kh * 4 + kw;
    int oc = h * 32 + ng * 8 + (t >> 2);
    int k0 = kt * 16 + (t & 3) * 2;
    uint2 v;
    __half2 b0 = __floats2half2_rn(w[k0 * 1024 + oc * 16 + tap],
                                   w[(k0 + 1) * 1024 + oc * 16 + tap]);
    __half2 b1 = __floats2half2_rn(w[(k0 + 8) * 1024 + oc * 16 + tap],
                                   w[(k0 + 9) * 1024 + oc * 16 + tap]);
    v.x = *(uint32_t*)&b0;
    v.y = *(uint32_t*)&b1;
    g_wfragB[wc][f][t] = v;
}

// ---- main fused kernel ----
__global__ void __launch_bounds__(256, 1)
fused_hmma_kernel(const float* __restrict__ x, const float* __restrict__ bias)
{
    extern __shared__ char smem[];
    __half* xs   = (__half*)smem;                        // [6*66][72]
    float*  qbuf = (float*)(smem + QBUF_OFF);            // [4q][64oc][132px]
    const uint32_t xs_b = smem_u32(smem);

    const int tid  = threadIdx.x;
    const int lane = tid & 31;
    const int wid  = tid >> 5;
    const int tile = blockIdx.x;
    const int b    = blockIdx.y;
    const int pr0  = tile * 4;

    // ---- load B-fragments (weights) into registers: 64 uint2 = 128 regs ----
    uint2 Bw[64];
    #pragma unroll
    for (int f = 0; f < 64; f++) Bw[f] = g_wfragB[wid][f][lane];

    // ---- stage x slab as fp16 [R][px][ic], zero-padded borders ----
    const float* xb = x + (size_t)b * C_ * HW_ * HW_;
    for (int ri = tid; ri < 384; ri += 256) {            // 6 rows * 64 ic
        int R = ri >> 6, ic = ri & 63, ih = pr0 - 1 + R;
        __half hv[66];
        #pragma unroll
        for (int p = 0; p < 66; p++) hv[p] = __float2half(0.f);
        if (ih >= 0 && ih < HW_) {
            const float4* src = (const float4*)(xb + ((size_t)ic * HW_ + ih) * HW_);
            #pragma unroll
            for (int p = 0; p < 16; p++) {
                float4 v = src[p];
                hv[1 + 4*p] = __float2half(v.x);
                hv[2 + 4*p] = __float2half(v.y);
                hv[3 + 4*p] = __float2half(v.z);
                hv[4 + 4*p] = __float2half(v.w);
            }
        }
        #pragma unroll
        for (int p = 0; p < 66; p++)
            xs[(R * 66 + p) * XS_HSTRIDE + ic] = hv[p];
    }
    __syncthreads();

    const int q = wid >> 1, h = wid & 1;
    const int a = q >> 1, bb = q & 1;
    const int ro[2] = { a ? 2 : 1, a ? 1 : 0 };          // jh = 0,1
    const int co[2] = { bb ? 2 : 1, bb ? 1 : 0 };        // jw = 0,1

    // per-lane invariant ldmatrix offset parts
    const int mblk = (lane >> 3) & 1;
    const int kblk = lane >> 4;
    const int lrow = lane & 7;

    float bb8[8], psum8[8];
    #pragma unroll
    for (int ol = 0; ol < 8; ol++) { bb8[ol] = bias[wid * 8 + ol]; psum8[ol] = 0.f; }

    for (int hf = 0; hf < 2; hf++) {
        // ---- mainloop: 8 n-tiles of 16 px covering 2 pooled rows x 64 px ----
        #pragma unroll 2
        for (int nt = 0; nt < 8; nt++) {
            const int lr  = hf * 2 + (nt >> 2);
            const int pc0 = (nt & 3) * 16;

            // A fragments: x tiles, [j][kt]
            uint4 Af[4][4];
            #pragma unroll
            for (int j = 0; j < 4; j++) {
                int R  = lr + ro[j >> 1];
                int px = pc0 + co[j & 1] + mblk * 8 + lrow;
                uint32_t rowbase = xs_b +
                    (((R * 66 + px) * XS_HSTRIDE) + kblk * 8) * 2;
                #pragma unroll
                for (int kt = 0; kt < 4; kt++)
                    ldsm_x4(Af[j][kt], rowbase + kt * 32);
            }

            float acc[4][4];
            #pragma unroll
            for (int ng = 0; ng < 4; ng++)
                #pragma unroll
                for (int i = 0; i < 4; i++) acc[ng][i] = 0.f;

            #pragma unroll
            for (int kt = 0; kt < 4; kt++)
                #pragma unroll
                for (int j = 0; j < 4; j++)
                    #pragma unroll
                    for (int ng = 0; ng < 4; ng++)
                        mma_xw(acc[ng], Af[j][kt], Bw[(kt * 4 + j) * 4 + ng]);

            // store: c0 = (px = t/4, oc = ng*8 + 2(t%4)), c1 = oc+1, c2/c3 = px+8
            int pxh = (nt >> 2) * 64 + pc0 + (lane >> 2);
            int ocb = h * 32 + 2 * (lane & 3);
            #pragma unroll
            for (int ng = 0; ng < 4; ng++) {
                float* d = qbuf + (q * 64 + ocb + ng * 8) * QPX + pxh;
                d[0]           = acc[ng][0];
                d[QPX]         = acc[ng][1];
                d[8]           = acc[ng][2];
                d[QPX + 8]     = acc[ng][3];
            }
        }
        __syncthreads();

        // ---- epilogue: warp w owns oc rows w*8..w*8+7; lane reads px lane*4..+3 ----
        #pragma unroll
        for (int ol = 0; ol < 8; ol++) {
            int oc = wid * 8 + ol;
            const float* base = qbuf + oc * QPX + lane * 4;
            float4 v0 = *(const float4*)(base + 0 * 64 * QPX);
            float4 v1 = *(const float4*)(base + 1 * 64 * QPX);
            float4 v2 = *(const float4*)(base + 2 * 64 * QPX);
            float4 v3 = *(const float4*)(base + 3 * 64 * QPX);
            float m, s = 0.f;
            m = fmaxf(fmaxf(v0.x, v1.x), fmaxf(v2.x, v3.x)) + bb8[ol];
            s += fminf(fmaxf(m, -1.f), 1.f);
            m = fmaxf(fmaxf(v0.y, v1.y), fmaxf(v2.y, v3.y)) + bb8[ol];
            s += fminf(fmaxf(m, -1.f), 1.f);
            m = fmaxf(fmaxf(v0.z, v1.z), fmaxf(v2.z, v3.z)) + bb8[ol];
            s += fminf(fmaxf(m, -1.f), 1.f);
            m = fmaxf(fmaxf(v0.w, v1.w), fmaxf(v2.w, v3.w)) + bb8[ol];
            s += fminf(fmaxf(m, -1.f), 1.f);
            psum8[ol] += s;
        }
        __syncthreads();
    }

    // ---- reduction: reuse qbuf as scratch [64 oc][32 lanes] ----
    float* red2 = qbuf;
    #pragma unroll
    for (int ol = 0; ol < 8; ol++)
        red2[(wid * 8 + ol) * 32 + lane] = psum8[ol];
    __syncthreads();
    if (tid < 64) {
        const float4* r = (const float4*)(red2 + tid * 32);
        float4 s4 = make_float4(0.f, 0.f, 0.f, 0.f);
        #pragma unroll
        for (int k = 0; k < 8; k++) {
            float4 v = r[k];
            s4.x += v.x; s4.y += v.y; s4.z += v.z; s4.w += v.w;
        }
        g_part[b][tid][tile] = (s4.x + s4.y) + (s4.z + s4.w);
    }
}

__global__ void finalize_kernel(float* __restrict__ out)
{
    int b  = blockIdx.x;
    int oc = threadIdx.x;
    float s = 0.f;
    #pragma unroll
    for (int t = 0; t < NTILE; ++t) s += g_part[b][oc][t];
    out[b * C_ + oc] = tanhf(s * (1.0f / 4096.0f));
}

extern "C" void kernel_launch(void* const* d_in, const int* in_sizes, int n_in,
                              void* d_out, int out_size)
{
    const float* x    = (const float*)d_in[0];
    const float* w    = (const float*)d_in[1];
    const float* bias = (const float*)d_in[2];
    float* out = (float*)d_out;

    cudaFuncSetAttribute(fused_hmma_kernel,
                         cudaFuncAttributeMaxDynamicSharedMemorySize, SMEM_TOTAL);

    prep_wfragB<<<64, 256>>>(w);
    fused_hmma_kernel<<<dim3(NTILE, B_), 256, SMEM_TOTAL>>>(x, bias);
    finalize_kernel<<<B_, C_>>>(out);
}

// round 6
// speedup vs baseline: 6.7813x; 1.0004x over previous
#include <cuda_runtime.h>
#include <cuda_fp16.h>
#include <cstdint>
#include <math.h>

#define B_    32
#define C_    64
#define HW_   64
#define NTILE 16

// ---- smem layout ----
#define XS_HSTRIDE 72                        // halves per (R,px) row (144B)
#define XS_BYTES   (6*66*XS_HSTRIDE*2)       // 57024
#define QBUF_OFF   XS_BYTES
#define QPX        132                       // padded px stride (floats)
#define QBUF_BYTES (4*64*QPX*4)              // 135168
#define SMEM_TOTAL (QBUF_OFF + QBUF_BYTES)   // 192192

// fragment-ordered B (weight) table: [warpclass 8][frag 64 = (kt*4+j)*4+ng][lane 32]
__device__ uint2 g_wfragB[8][64][32];
__device__ float g_part[B_][C_][NTILE];

// f16-accumulator HMMA: C/D = 2 regs (4 halves)
__device__ __forceinline__ void mma_xw_h(uint2& c, const uint4 a, const uint2 b) {
    asm volatile("mma.sync.aligned.m16n8k16.row.col.f16.f16.f16.f16 "
        "{%0,%1}, {%2,%3,%4,%5}, {%6,%7}, {%0,%1};"
        : "+r"(c.x), "+r"(c.y)
        : "r"(a.x), "r"(a.y), "r"(a.z), "r"(a.w), "r"(b.x), "r"(b.y));
}
__device__ __forceinline__ void ldsm_x4(uint4& d, uint32_t addr) {
    asm volatile("ldmatrix.sync.aligned.m8n8.x4.shared.b16 {%0,%1,%2,%3}, [%4];"
        : "=r"(d.x), "=r"(d.y), "=r"(d.z), "=r"(d.w) : "r"(addr));
}
__device__ __forceinline__ uint32_t smem_u32(const void* p) {
    uint32_t a;
    asm("{ .reg .u64 t; cvta.to.shared.u64 t, %1; cvt.u32.u64 %0, t; }" : "=r"(a) : "l"(p));
    return a;
}

// ---- prep: w[ic][oc][kh][kw] fp32 -> B-fragment fp16 table ----
__global__ void prep_wfragB(const float* __restrict__ w) {
    int idx = blockIdx.x * 256 + threadIdx.x;            // 8*64*32 = 16384
    if (idx >= 16384) return;
    int wc = idx >> 11, f = (idx >> 5) & 63, t = idx & 31;
    int q = wc >> 1, h = wc & 1;
    int kt = f >> 4, j = (f >> 2) & 3, ng = f & 3;
    int jh = j >> 1, jw = j & 1;
    int a = q >> 1, bb = q & 1;
    int kh = a ? (jh ? 2 : 0) : (jh ? 3 : 1);
    int kw = bb ? (jw ? 2 : 0) : (jw ? 3 : 1);
    int tap = kh * 4 + kw;
    int oc = h * 32 + ng * 8 + (t >> 2);
    int k0 = kt * 16 + (t & 3) * 2;
    uint2 v;
    __half2 b0 = __floats2half2_rn(w[k0 * 1024 + oc * 16 + tap],
                                   w[(k0 + 1) * 1024 + oc * 16 + tap]);
    __half2 b1 = __floats2half2_rn(w[(k0 + 8) * 1024 + oc * 16 + tap],
                                   w[(k0 + 9) * 1024 + oc * 16 + tap]);
    v.x = *(uint32_t*)&b0;
    v.y = *(uint32_t*)&b1;
    g_wfragB[wc][f][t] = v;
}

// ---- main fused kernel ----
__global__ void __launch_bounds__(256, 1)
fused_hmma_kernel(const float* __restrict__ x, const float* __restrict__ bias)
{
    extern __shared__ char smem[];
    __half* xs   = (__half*)smem;                        // [6*66][72]
    float*  qbuf = (float*)(smem + QBUF_OFF);            // [4q][64oc][132px]
    const uint32_t xs_b = smem_u32(smem);

    const int tid  = threadIdx.x;
    const int lane = tid & 31;
    const int wid  = tid >> 5;
    const int tile = blockIdx.x;
    const int b    = blockIdx.y;
    const int pr0  = tile * 4;

    // ---- load B-fragments (weights) into registers: 64 uint2 = 128 regs ----
    uint2 Bw[64];
    #pragma unroll
    for (int f = 0; f < 64; f++) Bw[f] = g_wfragB[wid][f][lane];

    // ---- stage x slab as fp16 [R][px][ic], zero-padded borders ----
    const float* xb = x + (size_t)b * C_ * HW_ * HW_;
    for (int ri = tid; ri < 384; ri += 256) {            // 6 rows * 64 ic
        int R = ri >> 6, ic = ri & 63, ih = pr0 - 1 + R;
        __half hv[66];
        #pragma unroll
        for (int p = 0; p < 66; p++) hv[p] = __float2half(0.f);
        if (ih >= 0 && ih < HW_) {
            const float4* src = (const float4*)(xb + ((size_t)ic * HW_ + ih) * HW_);
            #pragma unroll
            for (int p = 0; p < 16; p++) {
                float4 v = src[p];
                hv[1 + 4*p] = __float2half(v.x);
                hv[2 + 4*p] = __float2half(v.y);
                hv[3 + 4*p] = __float2half(v.z);
                hv[4 + 4*p] = __float2half(v.w);
            }
        }
        #pragma unroll
        for (int p = 0; p < 66; p++)
            xs[(R * 66 + p) * XS_HSTRIDE + ic] = hv[p];
    }
    __syncthreads();

    const int q = wid >> 1, h = wid & 1;
    const int a = q >> 1, bb = q & 1;
    const int ro[2] = { a ? 2 : 1, a ? 1 : 0 };          // jh = 0,1
    const int co[2] = { bb ? 2 : 1, bb ? 1 : 0 };        // jw = 0,1

    // per-lane invariant ldmatrix offset parts
    const int mblk = (lane >> 3) & 1;
    const int kblk = lane >> 4;
    const int lrow = lane & 7;

    float bb8[8], psum8[8];
    #pragma unroll
    for (int ol = 0; ol < 8; ol++) { bb8[ol] = bias[wid * 8 + ol]; psum8[ol] = 0.f; }

    for (int hf = 0; hf < 2; hf++) {
        // ---- mainloop: 8 n-tiles of 16 px covering 2 pooled rows x 64 px ----
        #pragma unroll 2
        for (int nt = 0; nt < 8; nt++) {
            const int lr  = hf * 2 + (nt >> 2);
            const int pc0 = (nt & 3) * 16;

            // A fragments: x tiles, [j][kt]
            uint4 Af[4][4];
            #pragma unroll
            for (int j = 0; j < 4; j++) {
                int R  = lr + ro[j >> 1];
                int px = pc0 + co[j & 1] + mblk * 8 + lrow;
                uint32_t rowbase = xs_b +
                    (((R * 66 + px) * XS_HSTRIDE) + kblk * 8) * 2;
                #pragma unroll
                for (int kt = 0; kt < 4; kt++)
                    ldsm_x4(Af[j][kt], rowbase + kt * 32);
            }

            uint2 acc[4];
            #pragma unroll
            for (int ng = 0; ng < 4; ng++) acc[ng] = make_uint2(0u, 0u);

            #pragma unroll
            for (int kt = 0; kt < 4; kt++)
                #pragma unroll
                for (int j = 0; j < 4; j++)
                    #pragma unroll
                    for (int ng = 0; ng < 4; ng++)
                        mma_xw_h(acc[ng], Af[j][kt], Bw[(kt * 4 + j) * 4 + ng]);

            // store: reg.x = half2(c0,c1) = (oc, oc+1) @ px=g ; reg.y = same @ px=g+8
            int pxh = (nt >> 2) * 64 + pc0 + (lane >> 2);
            int ocb = h * 32 + 2 * (lane & 3);
            #pragma unroll
            for (int ng = 0; ng < 4; ng++) {
                float2 f0 = __half22float2(*(__half2*)&acc[ng].x);
                float2 f1 = __half22float2(*(__half2*)&acc[ng].y);
                float* d = qbuf + (q * 64 + ocb + ng * 8) * QPX + pxh;
                d[0]       = f0.x;
                d[QPX]     = f0.y;
                d[8]       = f1.x;
                d[QPX + 8] = f1.y;
            }
        }
        __syncthreads();

        // ---- epilogue: warp w owns oc rows w*8..w*8+7; lane reads px lane*4..+3 ----
        #pragma unroll
        for (int ol = 0; ol < 8; ol++) {
            int oc = wid * 8 + ol;
            const float* base = qbuf + oc * QPX + lane * 4;
            float4 v0 = *(const float4*)(base + 0 * 64 * QPX);
            float4 v1 = *(const float4*)(base + 1 * 64 * QPX);
            float4 v2 = *(const float4*)(base + 2 * 64 * QPX);
            float4 v3 = *(const float4*)(base + 3 * 64 * QPX);
            float m, s = 0.f;
            m = fmaxf(fmaxf(v0.x, v1.x), fmaxf(v2.x, v3.x)) + bb8[ol];
            s += fminf(fmaxf(m, -1.f), 1.f);
            m = fmaxf(fmaxf(v0.y, v1.y), fmaxf(v2.y, v3.y)) + bb8[ol];
            s += fminf(fmaxf(m, -1.f), 1.f);
            m = fmaxf(fmaxf(v0.z, v1.z), fmaxf(v2.z, v3.z)) + bb8[ol];
            s += fminf(fmaxf(m, -1.f), 1.f);
            m = fmaxf(fmaxf(v0.w, v1.w), fmaxf(v2.w, v3.w)) + bb8[ol];
            s += fminf(fmaxf(m, -1.f), 1.f);
            psum8[ol] += s;
        }
        __syncthreads();
    }

    // ---- reduction: reuse qbuf as scratch [64 oc][32 lanes] ----
    float* red2 = qbuf;
    #pragma unroll
    for (int ol = 0; ol < 8; ol++)
        red2[(wid * 8 + ol) * 32 + lane] = psum8[ol];
    __syncthreads();
    if (tid < 64) {
        const float4* r = (const float4*)(red2 + tid * 32);
        float4 s4 = make_float4(0.f, 0.f, 0.f, 0.f);
        #pragma unroll
        for (int k = 0; k < 8; k++) {
            float4 v = r[k];
            s4.x += v.x; s4.y += v.y; s4.z += v.z; s4.w += v.w;
        }
        g_part[b][tid][tile] = (s4.x + s4.y) + (s4.z + s4.w);
    }
}

__global__ void finalize_kernel(float* __restrict__ out)
{
    int b  = blockIdx.x;
    int oc = threadIdx.x;
    float s = 0.f;
    #pragma unroll
    for (int t = 0; t < NTILE; ++t) s += g_part[b][oc][t];
    out[b * C_ + oc] = tanhf(s * (1.0f / 4096.0f));
}

extern "C" void kernel_launch(void* const* d_in, const int* in_sizes, int n_in,
                              void* d_out, int out_size)
{
    const float* x    = (const float*)d_in[0];
    const float* w    = (const float*)d_in[1];
    const float* bias = (const float*)d_in[2];
    float* out = (float*)d_out;

    cudaFuncSetAttribute(fused_hmma_kernel,
                         cudaFuncAttributeMaxDynamicSharedMemorySize, SMEM_TOTAL);

    prep_wfragB<<<64, 256>>>(w);
    fused_hmma_kernel<<<dim3(NTILE, B_), 256, SMEM_TOTAL>>>(x, bias);
    finalize_kernel<<<B_, C_>>>(out);
}